// round 15
// baseline (speedup 1.0000x reference)
#include <cuda_runtime.h>
#include <math.h>

// ---------------------------------------------------------------------------
// Scratch arena (floats). feats overlays plfw/plbw (dead after pk_lstm).
// ---------------------------------------------------------------------------
#define SZ_PREQG   (2048L*1024)
#define SZ_PREQC   (2048L*512)
#define SZ_PLFW    (32768L*2048)
#define SZ_PLBW    (32768L*2048)
#define SZ_PRER    (32768L*512)
#define SZ_PREC    (32768L*512)
#define SZ_FFW     (32768L*512)
#define SZ_FBW     (32768L*512)
#define SZ_FACT    (32768L*512)
#define SZ_ATTH    (32768L*512)
#define SZ_ATT     (32768L)
#define SZ_GATE    (32768L)
#define SZ_H       (32768L)
#define SZ_RH      (32768L)
#define SZ_U       (32768L)
#define SZ_QVEC    (32768L)
#define SZ_LH      (131072L)
#define SZ_LC      (65536L)
#define SZ_MEM     (65536L)
#define SZ_AS      (32768L)
#define SZ_AE      (32768L)
#define SZ_OUTS0   (32768L)
#define SZ_OUTE0   (32768L)
#define SZ_RMFW    (32768L)
#define SZ_RMBW    (32768L)
#define SZ_P       (524288L)

#define O_PREQG  0L
#define O_PREQC  (O_PREQG + SZ_PREQG)
#define O_PLFW   (O_PREQC + SZ_PREQC)
#define O_PLBW   (O_PLFW  + SZ_PLFW)
#define O_FEATS  O_PLFW
#define O_PRER   (O_PLBW  + SZ_PLBW)
#define O_PREC   (O_PRER  + SZ_PRER)
#define O_FFW    (O_PREC  + SZ_PREC)
#define O_FBW    (O_FFW   + SZ_FFW)
#define O_FACT   (O_FBW   + SZ_FBW)
#define O_ATTH   (O_FACT  + SZ_FACT)
#define O_ATT    (O_ATTH  + SZ_ATTH)
#define O_GATE   (O_ATT   + SZ_ATT)
#define O_H      (O_GATE  + SZ_GATE)
#define O_RH     (O_H     + SZ_H)
#define O_U      (O_RH    + SZ_RH)
#define O_QVEC   (O_U     + SZ_U)
#define O_LH     (O_QVEC  + SZ_QVEC)
#define O_LC     (O_LH    + SZ_LH)
#define O_MEM    (O_LC    + SZ_LC)
#define O_AS     (O_MEM   + SZ_MEM)
#define O_AE     (O_AS    + SZ_AS)
#define O_OUTS0  (O_AE    + SZ_AE)
#define O_OUTE0  (O_OUTS0 + SZ_OUTS0)
#define O_RMFW   (O_OUTE0 + SZ_OUTE0)
#define O_RMBW   (O_RMFW  + SZ_RMFW)
#define O_P1     (O_RMBW  + SZ_RMBW)
#define O_P2     (O_P1    + SZ_P)
#define SCR_TOTAL (O_P2 + SZ_P)

__device__ float g_scratch[SCR_TOTAL];
__device__ unsigned g_flags[256];

__device__ __forceinline__ float sigf(float x){ return 1.0f/(1.0f+expf(-x)); }

__device__ __forceinline__ unsigned long long fma2(unsigned long long a,
                                                   unsigned long long b,
                                                   unsigned long long c){
    unsigned long long d;
    asm("fma.rn.f32x2 %0, %1, %2, %3;" : "=l"(d) : "l"(a), "l"(b), "l"(c));
    return d;
}
__device__ __forceinline__ float2 ull2f2(unsigned long long u){
    float2 f;
    asm("mov.b64 {%0, %1}, %2;" : "=f"(f.x), "=f"(f.y) : "l"(u));
    return f;
}
__device__ __forceinline__ unsigned long long dup2(float b){
    unsigned long long d;
    asm("mov.b64 %0, {%1, %1};" : "=l"(d) : "f"(b));
    return d;
}

// release/acquire grid barrier; all blocks co-resident.
__device__ __forceinline__ void flatbar(int nb, unsigned gen){
    __syncthreads();
    if (threadIdx.x == 0){
        asm volatile("st.release.gpu.global.u32 [%0], %1;"
                     :: "l"(g_flags + blockIdx.x), "r"(gen) : "memory");
    }
    if (threadIdx.x < nb){
        unsigned v;
        do {
            asm volatile("ld.acquire.gpu.global.u32 %0, [%1];"
                         : "=r"(v) : "l"(g_flags + threadIdx.x) : "memory");
        } while (v < gen);
    }
    __syncthreads();
}

// ---------------------------------------------------------------------------
// tiny helpers
// ---------------------------------------------------------------------------
__global__ void k_init(float* __restrict__ S){
    long i = (long)blockIdx.x*256 + threadIdx.x;   // grid 512 -> 131072
    if (i < 32768){ S[O_H+i]=0.f; S[O_AS+i]=0.f; S[O_AE+i]=0.f; }
    if (i < 65536) S[O_LC+i]=0.f;
    S[O_LH+i]=0.f;
    if (i < 256) g_flags[i] = 0u;
}
__global__ void k_zerou(unsigned* __restrict__ p){
    p[threadIdx.x] = 0u;
}
__global__ void k_copy2(float* __restrict__ d1, float* __restrict__ d2, const float* __restrict__ s){
    int i = blockIdx.x*256 + threadIdx.x;
    float v = s[i];
    d1[i] = v; d2[i] = v;
}
__global__ void k_rowmaps(const int* __restrict__ ids, const int* __restrict__ ilen,
                          int* __restrict__ rmfw, int* __restrict__ rmbw){
    int idx = blockIdx.x*256 + threadIdx.x;
    int b = idx >> 9, t = idx & 511;
    rmfw[idx] = ids[idx];
    int L = ilen[b];
    int rt = (t < L) ? (L - 1 - t) : t;
    rmbw[idx] = ids[b*512 + rt];
}
// fattened: grid 512, grid-stride over 4,194,304 float4
__global__ void k_combine(float* __restrict__ dst, const float* __restrict__ a, const float* __restrict__ b){
    for (long i = (long)blockIdx.x*256 + threadIdx.x; i < 4194304L; i += 512L*256){
        float4 x = ((const float4*)a)[i];
        float4 y = ((const float4*)b)[i];
        ((float4*)dst)[i] = make_float4(x.x+y.x, x.y+y.y, x.z+y.z, x.w+y.w);
    }
}
__global__ void k_gather_rows(float* __restrict__ dst, const float* __restrict__ emb, const int* __restrict__ idx){
    int b = blockIdx.x, tid = threadIdx.x;
    long r = idx[b];
    dst[b*512 + tid]       = emb[r*512 + tid];
    dst[b*512 + 256 + tid] = emb[r*512 + 256 + tid];
}
__global__ void k_argmax_gather(const float* __restrict__ logits, const float* __restrict__ emb, float* __restrict__ dst){
    __shared__ float sv[256];
    __shared__ int   si[256];
    int b = blockIdx.x, tid = threadIdx.x;
    float v0 = logits[b*512 + tid];
    float v1 = logits[b*512 + 256 + tid];
    float bv; int bi;
    if (v1 > v0){ bv = v1; bi = tid + 256; } else { bv = v0; bi = tid; }
    sv[tid] = bv; si[tid] = bi;
    __syncthreads();
    for (int s = 128; s > 0; s >>= 1){
        if (tid < s){
            float ov = sv[tid+s]; int oi = si[tid+s];
            if (ov > sv[tid] || (ov == sv[tid] && oi < si[tid])){ sv[tid] = ov; si[tid] = oi; }
        }
        __syncthreads();
    }
    long idx = si[0];
    dst[b*512 + tid]       = emb[idx*512 + tid];
    dst[b*512 + 256 + tid] = emb[idx*512 + 256 + tid];
}

// ---------------------------------------------------------------------------
// feature constructor
// ---------------------------------------------------------------------------
__device__ __forceinline__ float4 feat4(int k, const float4* fp, const float4* qp, const float4* mp){
    int seg = k >> 9, ki = (k & 511) >> 2;
    if (seg == 0) return fp[ki];
    if (seg == 1) return mp[ki];
    if (seg == 2) return qp[ki];
    float4 f = fp[ki];
    float4 q = (seg == 3 || seg == 5) ? qp[ki] : mp[ki];
    if (seg <= 4) return make_float4(f.x*q.x, f.y*q.y, f.z*q.z, f.w*q.w);
    return make_float4(fabsf(f.x-q.x), fabsf(f.y-q.y), fabsf(f.z-q.z), fabsf(f.w-q.w));
}

// fattened: grid 2048, each block owns 16 rows, threads stride cols
__global__ void k_buildfeats(float* __restrict__ feats, const float* __restrict__ fact,
                             const float* __restrict__ qvec, const float* __restrict__ mem){
    const int tid = threadIdx.x;
    for (int r = 0; r < 16; r++){
        int m = blockIdx.x*16 + r;
        int b = m >> 9;
        const float4* fp = (const float4*)(fact + (long)m*512);
        const float4* qp = (const float4*)(qvec + (long)b*512);
        const float4* mp = (const float4*)(mem  + (long)b*512);
        float4* drow = (float4*)(feats + (long)m*3584);
        #pragma unroll
        for (int c = tid; c < 896; c += 256)
            drow[c] = feat4(c*4, fp, qp, mp);
    }
}

// ---------------------------------------------------------------------------
// Big GEMM v3 (unchanged)
// ---------------------------------------------------------------------------
template<int ACT>
__global__ void __launch_bounds__(256) gemm128(
    const float* __restrict__ A, int lda, const int* __restrict__ rowmap,
    const float* __restrict__ B, int ldb,
    const float* __restrict__ bias,
    float* __restrict__ C, int ldc, int K)
{
    __shared__ float As[2][16][132];
    __shared__ float Bs[2][16][132];
    const int m0 = blockIdx.y*128, n0 = blockIdx.x*128;
    const int tid = threadIdx.x;
    const int tx = tid & 15, ty = tid >> 4;
    const int arow = tid >> 1, kg = (tid & 1)*8;
    const int brow = tid >> 4, bcol = (tid & 15)*8;
    long ar = rowmap ? (long)rowmap[m0 + arow] : (long)(m0 + arow);
    const float* Ap = A + ar*lda;
    const float* Bp = B + (long)brow*ldb + n0 + bcol;
    const int nc = K >> 4;

    unsigned long long acc[4][8];
    #pragma unroll
    for (int i = 0; i < 4; i++)
        #pragma unroll
        for (int j = 0; j < 8; j++) acc[i][j] = 0ull;

    float4 aR0 = *(const float4*)(Ap + kg);
    float4 aR1 = *(const float4*)(Ap + kg + 4);
    float4 bR0 = *(const float4*)(Bp);
    float4 bR1 = *(const float4*)(Bp + 4);
    {
        As[0][kg+0][arow]=aR0.x; As[0][kg+1][arow]=aR0.y;
        As[0][kg+2][arow]=aR0.z; As[0][kg+3][arow]=aR0.w;
        As[0][kg+4][arow]=aR1.x; As[0][kg+5][arow]=aR1.y;
        As[0][kg+6][arow]=aR1.z; As[0][kg+7][arow]=aR1.w;
        *(float4*)&Bs[0][brow][bcol]     = bR0;
        *(float4*)&Bs[0][brow][bcol + 4] = bR1;
    }
    __syncthreads();

    for (int c = 0; c < nc; c++){
        const int s = c & 1;
        if (c + 1 < nc){
            int k0 = (c+1) << 4;
            aR0 = *(const float4*)(Ap + k0 + kg);
            aR1 = *(const float4*)(Ap + k0 + kg + 4);
            bR0 = *(const float4*)(Bp + (long)k0*ldb);
            bR1 = *(const float4*)(Bp + (long)k0*ldb + 4);
        }
        #pragma unroll
        for (int kk = 0; kk < 16; kk++){
            unsigned long long a2[4];
            *(float4*)(a2)   = *(const float4*)&As[s][kk][ty*8];
            *(float4*)(a2+2) = *(const float4*)&As[s][kk][ty*8+4];
            float bsc[8];
            *(float4*)(bsc)   = *(const float4*)&Bs[s][kk][tx*8];
            *(float4*)(bsc+4) = *(const float4*)&Bs[s][kk][tx*8+4];
            #pragma unroll
            for (int j = 0; j < 8; j++){
                unsigned long long b2 = dup2(bsc[j]);
                #pragma unroll
                for (int i = 0; i < 4; i++)
                    acc[i][j] = fma2(a2[i], b2, acc[i][j]);
            }
        }
        if (c + 1 < nc){
            const int d = s ^ 1;
            As[d][kg+0][arow]=aR0.x; As[d][kg+1][arow]=aR0.y;
            As[d][kg+2][arow]=aR0.z; As[d][kg+3][arow]=aR0.w;
            As[d][kg+4][arow]=aR1.x; As[d][kg+5][arow]=aR1.y;
            As[d][kg+6][arow]=aR1.z; As[d][kg+7][arow]=aR1.w;
            *(float4*)&Bs[d][brow][bcol]     = bR0;
            *(float4*)&Bs[d][brow][bcol + 4] = bR1;
            __syncthreads();
        }
    }
    float bl[8];
    *(float4*)(bl)   = *(const float4*)&bias[n0 + tx*8];
    *(float4*)(bl+4) = *(const float4*)&bias[n0 + tx*8 + 4];
    #pragma unroll
    for (int i = 0; i < 4; i++){
        float lo[8], hi[8];
        #pragma unroll
        for (int j = 0; j < 8; j++){
            float2 v = ull2f2(acc[i][j]);
            lo[j] = v.x + bl[j];
            hi[j] = v.y + bl[j];
            if (ACT == 2){ lo[j] = tanhf(lo[j]); hi[j] = tanhf(hi[j]); }
        }
        long me = m0 + ty*8 + 2*i, mo = me + 1;
        *(float4*)&C[me*ldc + n0 + tx*8]     = *(float4*)(lo);
        *(float4*)&C[me*ldc + n0 + tx*8 + 4] = *(float4*)(lo+4);
        *(float4*)&C[mo*ldc + n0 + tx*8]     = *(float4*)(hi);
        *(float4*)&C[mo*ldc + n0 + tx*8 + 4] = *(float4*)(hi+4);
    }
}

// fattened: grid 512 x 8 warps, each warp strides rows
__global__ void k_att2(const float* __restrict__ atth, const float* __restrict__ W2,
                       const float* __restrict__ b2, float* __restrict__ att){
    int w = blockIdx.x*8 + (threadIdx.x >> 5);
    int lane = threadIdx.x & 31;
    float wv[16];
    #pragma unroll
    for (int i = 0; i < 16; i++) wv[i] = W2[lane + i*32];
    float bb = b2[0];
    for (int m = w; m < 32768; m += 512*8){
        const float* row = atth + (long)m*512;
        float s = 0.f;
        #pragma unroll
        for (int i = 0; i < 16; i++) s = fmaf(row[lane + i*32], wv[i], s);
        #pragma unroll
        for (int o = 16; o > 0; o >>= 1) s += __shfl_xor_sync(0xffffffffu, s, o);
        if (lane == 0) att[m] = s + bb;
    }
}

__global__ void k_softmax(const float* __restrict__ att, float* __restrict__ gate){
    __shared__ float red[256];
    int b = blockIdx.x, tid = threadIdx.x;
    float v0 = att[b*512 + tid], v1 = att[b*512 + 256 + tid];
    red[tid] = fmaxf(v0, v1);
    __syncthreads();
    for (int s = 128; s > 0; s >>= 1){ if (tid < s) red[tid] = fmaxf(red[tid], red[tid+s]); __syncthreads(); }
    float mx = red[0];
    __syncthreads();
    float e0 = expf(v0 - mx), e1 = expf(v1 - mx);
    red[tid] = e0 + e1;
    __syncthreads();
    for (int s = 128; s > 0; s >>= 1){ if (tid < s) red[tid] += red[tid+s]; __syncthreads(); }
    float inv = 1.f/red[0];
    gate[b*512 + tid]       = e0*inv;
    gate[b*512 + 256 + tid] = e1*inv;
}

// ---------------------------------------------------------------------------
// Persistent question GRU (unchanged, R8)
// ---------------------------------------------------------------------------
__global__ void __launch_bounds__(256) pk_gru(
    const float* __restrict__ Wg, const float* __restrict__ Wc,
    const float* __restrict__ preg, const float* __restrict__ prec,
    const int* __restrict__ qlen,
    float* __restrict__ h, float* __restrict__ rh, float* __restrict__ u)
{
    __shared__ float As[16][64];
    __shared__ float Bs[16][32];
    const int tid = threadIdx.x, bx = blockIdx.x;
    const int tx = tid & 31, ty = tid >> 5;
    const int arow = tid >> 2, acol = (tid & 3)*4;
    unsigned gen = 0;
    for (int t = 0; t < 32; t++){
        {
            const int n0 = bx*32;
            float acc[8] = {};
            for (int k0 = 0; k0 < 512; k0 += 16){
                float4 a4 = __ldcg((const float4*)(h + arow*512 + k0 + acol));
                As[acol+0][arow]=a4.x; As[acol+1][arow]=a4.y;
                As[acol+2][arow]=a4.z; As[acol+3][arow]=a4.w;
                if (tid < 128){
                    int kk = tid >> 3, c4 = (tid & 7)*4;
                    *(float4*)&Bs[kk][c4] = *(const float4*)(Wg + (long)(k0+kk)*1024 + n0 + c4);
                }
                __syncthreads();
                #pragma unroll
                for (int kk = 0; kk < 16; kk++){
                    float ra[8];
                    *(float4*)(ra)   = *(const float4*)&As[kk][ty*8];
                    *(float4*)(ra+4) = *(const float4*)&As[kk][ty*8+4];
                    float rb = Bs[kk][tx];
                    #pragma unroll
                    for (int i = 0; i < 8; i++) acc[i] = fmaf(ra[i], rb, acc[i]);
                }
                __syncthreads();
            }
            int n = n0 + tx;
            #pragma unroll
            for (int i = 0; i < 8; i++){
                int b = ty*8 + i;
                float z = acc[i] + preg[((long)b*32 + t)*1024 + n];
                float s = sigf(z);
                if (n < 512) __stcg(rh + b*512 + n, s * __ldcg(h + b*512 + n));
                else         __stcg(u + b*512 + (n - 512), s);
            }
        }
        flatbar(32, ++gen);
        if (bx < 16){
            const int n0 = bx*32;
            float acc[8] = {};
            for (int k0 = 0; k0 < 512; k0 += 16){
                float4 a4 = __ldcg((const float4*)(rh + arow*512 + k0 + acol));
                As[acol+0][arow]=a4.x; As[acol+1][arow]=a4.y;
                As[acol+2][arow]=a4.z; As[acol+3][arow]=a4.w;
                if (tid < 128){
                    int kk = tid >> 3, c4 = (tid & 7)*4;
                    *(float4*)&Bs[kk][c4] = *(const float4*)(Wc + (long)(k0+kk)*512 + n0 + c4);
                }
                __syncthreads();
                #pragma unroll
                for (int kk = 0; kk < 16; kk++){
                    float ra[8];
                    *(float4*)(ra)   = *(const float4*)&As[kk][ty*8];
                    *(float4*)(ra+4) = *(const float4*)&As[kk][ty*8+4];
                    float rb = Bs[kk][tx];
                    #pragma unroll
                    for (int i = 0; i < 8; i++) acc[i] = fmaf(ra[i], rb, acc[i]);
                }
                __syncthreads();
            }
            int n = n0 + tx;
            #pragma unroll
            for (int i = 0; i < 8; i++){
                int b = ty*8 + i;
                float c = tanhf(acc[i] + prec[((long)b*32 + t)*512 + n]);
                float uu = __ldcg(u + b*512 + n);
                float ho = __ldcg(h + b*512 + n);
                float hn = (t < qlen[b]) ? (uu*ho + (1.f - uu)*c) : ho;
                __stcg(h + b*512 + n, hn);
            }
        }
        flatbar(32, ++gen);
    }
}

// ---------------------------------------------------------------------------
// Persistent bi-LSTM (exact R8 version)
// ---------------------------------------------------------------------------
__global__ void __launch_bounds__(256) pk_lstm(
    const float* __restrict__ Wfwh, const float* __restrict__ Wbwh,
    const float* __restrict__ prefw, const float* __restrict__ prebw,
    const int* __restrict__ ilen,
    float* __restrict__ lh, float* __restrict__ lc,
    float* __restrict__ ffw, float* __restrict__ fbw)
{
    __shared__ float As[16][64];
    __shared__ float Bs[16][32];
    __shared__ float zs[64][32];
    const int tid = threadIdx.x;
    const int dir = blockIdx.x >> 6;
    const int hc8 = (blockIdx.x & 63)*8;
    const float* Wh  = dir ? Wbwh : Wfwh;
    const float* pre = dir ? prebw : prefw;
    float* cbuf = lc + dir*32768;
    float* outp = dir ? fbw : ffw;
    const int tx = tid & 31, ty = tid >> 5;
    const int arow = tid >> 2, acol = (tid & 3)*4;
    const int eb0 = (tid*2) >> 3,     ej0 = (tid*2) & 7;
    const int eb1 = (tid*2+1) >> 3,   ej1 = (tid*2+1) & 7;
    const int ehc0 = hc8 + ej0, ehc1 = hc8 + ej1;
    const int L0 = ilen[eb0], L1 = ilen[eb1];
    unsigned gen = 0;
    for (int t = 0; t < 512; t++){
        const int par = t & 1;
        const float* hin = lh + par*65536 + dir*32768;
        float* hout = lh + (par^1)*65536 + dir*32768;

        long pr0 = ((long)eb0*512 + t)*2048;
        long pr1 = ((long)eb1*512 + t)*2048;
        float pz0_i = __ldcg(pre + pr0 + ehc0);
        float pz0_j = __ldcg(pre + pr0 + 512 + ehc0);
        float pz0_f = __ldcg(pre + pr0 + 1024 + ehc0);
        float pz0_o = __ldcg(pre + pr0 + 1536 + ehc0);
        float pz1_i = __ldcg(pre + pr1 + ehc1);
        float pz1_j = __ldcg(pre + pr1 + 512 + ehc1);
        float pz1_f = __ldcg(pre + pr1 + 1024 + ehc1);
        float pz1_o = __ldcg(pre + pr1 + 1536 + ehc1);
        float hold0 = __ldcg(hin + eb0*512 + ehc0);
        float hold1 = __ldcg(hin + eb1*512 + ehc1);

        float acc[8] = {};
        for (int k0 = 0; k0 < 512; k0 += 16){
            float4 a4 = __ldcg((const float4*)(hin + arow*512 + k0 + acol));
            As[acol+0][arow]=a4.x; As[acol+1][arow]=a4.y;
            As[acol+2][arow]=a4.z; As[acol+3][arow]=a4.w;
            if (tid < 128){
                int kk = tid >> 3, rem = tid & 7;
                int gg = rem >> 1, h4 = (rem & 1)*4;
                *(float4*)&Bs[kk][gg*8 + h4] =
                    *(const float4*)(Wh + (long)(k0+kk)*2048 + gg*512 + hc8 + h4);
            }
            __syncthreads();
            #pragma unroll
            for (int kk = 0; kk < 16; kk++){
                float ra[8];
                *(float4*)(ra)   = *(const float4*)&As[kk][ty*8];
                *(float4*)(ra+4) = *(const float4*)&As[kk][ty*8+4];
                float rb = Bs[kk][tx];
                #pragma unroll
                for (int i = 0; i < 8; i++) acc[i] = fmaf(ra[i], rb, acc[i]);
            }
            __syncthreads();
        }
        #pragma unroll
        for (int i = 0; i < 8; i++) zs[ty*8 + i][tx] = acc[i];
        __syncthreads();
        {
            float zi = zs[eb0][ej0]      + pz0_i;
            float zj = zs[eb0][8 + ej0]  + pz0_j;
            float zf = zs[eb0][16 + ej0] + pz0_f;
            float zo = zs[eb0][24 + ej0] + pz0_o;
            float c_old = cbuf[eb0*512 + ehc0];
            float cn = sigf(zf + 1.f)*c_old + sigf(zi)*tanhf(zj);
            float hn = sigf(zo)*tanhf(cn);
            bool m = t < L0;
            __stcg(hout + eb0*512 + ehc0, m ? hn : hold0);
            cbuf[eb0*512 + ehc0] = m ? cn : c_old;
            int wt = dir ? (m ? (L0 - 1 - t) : t) : t;
            __stcg(outp + ((long)eb0*512 + wt)*512 + ehc0, m ? hn : 0.f);
        }
        {
            float zi = zs[eb1][ej1]      + pz1_i;
            float zj = zs[eb1][8 + ej1]  + pz1_j;
            float zf = zs[eb1][16 + ej1] + pz1_f;
            float zo = zs[eb1][24 + ej1] + pz1_o;
            float c_old = cbuf[eb1*512 + ehc1];
            float cn = sigf(zf + 1.f)*c_old + sigf(zi)*tanhf(zj);
            float hn = sigf(zo)*tanhf(cn);
            bool m = t < L1;
            __stcg(hout + eb1*512 + ehc1, m ? hn : hold1);
            cbuf[eb1*512 + ehc1] = m ? cn : c_old;
            int wt = dir ? (m ? (L1 - 1 - t) : t) : t;
            __stcg(outp + ((long)eb1*512 + wt)*512 + ehc1, m ? hn : 0.f);
        }
        flatbar(128, ++gen);
    }
}

// ---------------------------------------------------------------------------
// Persistent AGRU v4 (R12): 128 blocks = 8 nt x 16 kt, nsteps param.
// ---------------------------------------------------------------------------
__global__ void __launch_bounds__(256) pk_agru(
    const float* __restrict__ Ur, const float* __restrict__ Uc,
    const float* __restrict__ prer, const float* __restrict__ prec,
    const float* __restrict__ gate, const int* __restrict__ ilen,
    float* __restrict__ hout_g, float* __restrict__ P1, float* __restrict__ P2,
    int nsteps)
{
    __shared__ float Urs[32][68];
    __shared__ float Ucs[32][68];
    __shared__ float hs[32][72];
    __shared__ float rhs[32][72];
    __shared__ int   ilens[64];

    const int tid = threadIdx.x;
    const int nt = blockIdx.x & 7;
    const int kt = blockIdx.x >> 3;
    const int kbase = kt*32, nbase = nt*64;

    const int ty = tid >> 4;
    const int tx = tid & 15;
    const int nl = tid >> 3;
    const int bb = (tid & 7)*8;
    const int ngl = kbase + nl;

    for (int i = tid; i < 32*64; i += 256){
        int k = i >> 6, n = i & 63;
        Urs[k][n] = Ur[(long)(kbase + k)*512 + nbase + n];
        Ucs[k][n] = Uc[(long)(kbase + k)*512 + nbase + n];
    }
    for (int i = tid; i < 32*64; i += 256) hs[i >> 6][i & 63] = 0.f;
    if (tid < 64) ilens[tid] = ilen[tid];
    __syncthreads();

    unsigned gen = 0;
    for (int t = 0; t < nsteps; t++){
        {
            unsigned long long acc[4][2];
            #pragma unroll
            for (int j = 0; j < 4; j++){ acc[j][0] = 0ull; acc[j][1] = 0ull; }
            #pragma unroll 8
            for (int k = 0; k < 32; k++){
                unsigned long long ap[2];
                *(float4*)(ap) = *(const float4*)&hs[k][4*ty];
                float4 bv = *(const float4*)&Urs[k][4*tx];
                unsigned long long b0 = dup2(bv.x), b1 = dup2(bv.y);
                unsigned long long b2 = dup2(bv.z), b3 = dup2(bv.w);
                acc[0][0]=fma2(ap[0],b0,acc[0][0]); acc[0][1]=fma2(ap[1],b0,acc[0][1]);
                acc[1][0]=fma2(ap[0],b1,acc[1][0]); acc[1][1]=fma2(ap[1],b1,acc[1][1]);
                acc[2][0]=fma2(ap[0],b2,acc[2][0]); acc[2][1]=fma2(ap[1],b2,acc[2][1]);
                acc[3][0]=fma2(ap[0],b3,acc[3][0]); acc[3][1]=fma2(ap[1],b3,acc[3][1]);
            }
            #pragma unroll
            for (int j = 0; j < 4; j++){
                long base = (long)kt*32768 + (long)(nbase + 4*tx + j)*64 + 4*ty;
                __stcg((float4*)(P1 + base), *(float4*)&acc[j][0]);
            }
        }
        flatbar(128, ++gen);
        {
            float z[8];
            #pragma unroll
            for (int i = 0; i < 8; i++)
                z[i] = __ldcg(prer + ((long)(bb+i)*512 + t)*512 + ngl);
            #pragma unroll
            for (int j = 0; j < 16; j++){
                const float* pp = P1 + (long)j*32768 + (long)ngl*64 + bb;
                float4 p0 = __ldcg((const float4*)pp);
                float4 p1 = __ldcg((const float4*)(pp + 4));
                z[0] += p0.x; z[1] += p0.y; z[2] += p0.z; z[3] += p0.w;
                z[4] += p1.x; z[5] += p1.y; z[6] += p1.z; z[7] += p1.w;
            }
            float hold[8];
            *(float4*)(hold)   = *(const float4*)&hs[nl][bb];
            *(float4*)(hold+4) = *(const float4*)&hs[nl][bb+4];
            float rv[8];
            #pragma unroll
            for (int i = 0; i < 8; i++) rv[i] = sigf(z[i]) * hold[i];
            *(float4*)&rhs[nl][bb]   = *(float4*)(rv);
            *(float4*)&rhs[nl][bb+4] = *(float4*)(rv+4);
        }
        __syncthreads();
        {
            unsigned long long acc[4][2];
            #pragma unroll
            for (int j = 0; j < 4; j++){ acc[j][0] = 0ull; acc[j][1] = 0ull; }
            #pragma unroll 8
            for (int k = 0; k < 32; k++){
                unsigned long long ap[2];
                *(float4*)(ap) = *(const float4*)&rhs[k][4*ty];
                float4 bv = *(const float4*)&Ucs[k][4*tx];
                unsigned long long b0 = dup2(bv.x), b1 = dup2(bv.y);
                unsigned long long b2 = dup2(bv.z), b3 = dup2(bv.w);
                acc[0][0]=fma2(ap[0],b0,acc[0][0]); acc[0][1]=fma2(ap[1],b0,acc[0][1]);
                acc[1][0]=fma2(ap[0],b1,acc[1][0]); acc[1][1]=fma2(ap[1],b1,acc[1][1]);
                acc[2][0]=fma2(ap[0],b2,acc[2][0]); acc[2][1]=fma2(ap[1],b2,acc[2][1]);
                acc[3][0]=fma2(ap[0],b3,acc[3][0]); acc[3][1]=fma2(ap[1],b3,acc[3][1]);
            }
            #pragma unroll
            for (int j = 0; j < 4; j++){
                long base = (long)kt*32768 + (long)(nbase + 4*tx + j)*64 + 4*ty;
                __stcg((float4*)(P2 + base), *(float4*)&acc[j][0]);
            }
        }
        flatbar(128, ++gen);
        {
            float z[8], gg[8];
            #pragma unroll
            for (int i = 0; i < 8; i++){
                z[i]  = __ldcg(prec + ((long)(bb+i)*512 + t)*512 + ngl);
                gg[i] = __ldg(gate + (bb+i)*512 + t);
            }
            #pragma unroll
            for (int j = 0; j < 16; j++){
                const float* pp = P2 + (long)j*32768 + (long)ngl*64 + bb;
                float4 p0 = __ldcg((const float4*)pp);
                float4 p1 = __ldcg((const float4*)(pp + 4));
                z[0] += p0.x; z[1] += p0.y; z[2] += p0.z; z[3] += p0.w;
                z[4] += p1.x; z[5] += p1.y; z[6] += p1.z; z[7] += p1.w;
            }
            float hold[8];
            *(float4*)(hold)   = *(const float4*)&hs[nl][bb];
            *(float4*)(hold+4) = *(const float4*)&hs[nl][bb+4];
            float hv[8];
            #pragma unroll
            for (int i = 0; i < 8; i++){
                float hh = tanhf(z[i]);
                bool m = t < ilens[bb+i];
                hv[i] = m ? (gg[i]*hh + (1.f - gg[i])*hold[i]) : hold[i];
            }
            *(float4*)&hs[nl][bb]   = *(float4*)(hv);
            *(float4*)&hs[nl][bb+4] = *(float4*)(hv+4);
        }
        __syncthreads();
    }
    if (nt == 0){
        #pragma unroll
        for (int i = 0; i < 8; i++)
            __stcg(hout_g + (long)(bb+i)*512 + ngl, hs[nl][bb+i]);
    }
}

// ---------------------------------------------------------------------------
// Concat-A GEMM (unchanged)
// ---------------------------------------------------------------------------
template<int ACT>
__global__ void __launch_bounds__(256) k_catgemm(
    const float* __restrict__ p0, const float* __restrict__ p1,
    const float* __restrict__ p2, const float* __restrict__ p3,
    const float* __restrict__ p4,
    const float* __restrict__ W, const float* __restrict__ bias,
    float* __restrict__ C, int K)
{
    const float* segs[5] = {p0, p1, p2, p3, p4};
    __shared__ float As[16][64];
    __shared__ float Bs[16][64];
    const int n0 = blockIdx.x*64;
    const int tid = threadIdx.x;
    const int tx = tid & 31, ty = tid >> 5;
    const int arow = tid >> 2, acol = (tid & 3)*4;
    const int brow = tid >> 4, bcol = (tid & 15)*4;
    float acc[8][2] = {};
    for (int k0 = 0; k0 < K; k0 += 16){
        int k = k0 + acol;
        const float* sp = segs[k >> 9];
        float4 a4 = *(const float4*)(sp + arow*512 + (k & 511));
        As[acol+0][arow] = a4.x; As[acol+1][arow] = a4.y;
        As[acol+2][arow] = a4.z; As[acol+3][arow] = a4.w;
        *(float4*)&Bs[brow][bcol] = *(const float4*)(W + (long)(k0+brow)*512 + n0 + bcol);
        __syncthreads();
        #pragma unroll
        for (int kk = 0; kk < 16; kk++){
            float ra[8];
            *(float4*)(ra)   = *(const float4*)&As[kk][ty*8];
            *(float4*)(ra+4) = *(const float4*)&As[kk][ty*8+4];
            float2 rb = *(const float2*)&Bs[kk][tx*2];
            #pragma unroll
            for (int i = 0; i < 8; i++){
                acc[i][0] = fmaf(ra[i], rb.x, acc[i][0]);
                acc[i][1] = fmaf(ra[i], rb.y, acc[i][1]);
            }
        }
        __syncthreads();
    }
    #pragma unroll
    for (int i = 0; i < 8; i++){
        int b = ty*8 + i;
        #pragma unroll
        for (int j = 0; j < 2; j++){
            int n = n0 + tx*2 + j;
            float v = acc[i][j] + bias[n];
            if (ACT == 1) v = fmaxf(v, 0.f);
            C[b*512 + n] = v;
        }
    }
}

// ---------------------------------------------------------------------------
// host launcher
// ---------------------------------------------------------------------------
extern "C" void kernel_launch(void* const* d_in, const int* in_sizes, int n_in,
                              void* d_out, int out_size)
{
    (void)in_sizes; (void)n_in; (void)out_size;
    const int*   question  = (const int*)  d_in[0];
    const int*   input_ids = (const int*)  d_in[1];
    const int*   qlen      = (const int*)  d_in[2];
    const int*   ilen      = (const int*)  d_in[3];
    const int*   start     = (const int*)  d_in[4];
    const float* emb       = (const float*)d_in[5];
    const float* qWg       = (const float*)d_in[6];
    const float* qbg       = (const float*)d_in[7];
    const float* qWc       = (const float*)d_in[8];
    const float* qbc       = (const float*)d_in[9];
    const float* lfW       = (const float*)d_in[10];
    const float* lfb       = (const float*)d_in[11];
    const float* lbW       = (const float*)d_in[12];
    const float* lbb       = (const float*)d_in[13];
    const float* aW1       = (const float*)d_in[14];
    const float* ab1       = (const float*)d_in[15];
    const float* aW2       = (const float*)d_in[16];
    const float* ab2       = (const float*)d_in[17];
    const float* Wr        = (const float*)d_in[18];
    const float* Ur        = (const float*)d_in[19];
    const float* br        = (const float*)d_in[20];
    const float* Wc        = (const float*)d_in[21];
    const float* Uc        = (const float*)d_in[22];
    const float* bc        = (const float*)d_in[23];
    const float* hopW      = (const float*)d_in[24];
    const float* hopB      = (const float*)d_in[25];
    const float* osW       = (const float*)d_in[26];
    const float* osB       = (const float*)d_in[27];
    const float* oeW       = (const float*)d_in[28];
    const float* oeB       = (const float*)d_in[29];
    float* out = (float*)d_out;

    float* S = nullptr;
    cudaGetSymbolAddress((void**)&S, g_scratch);
    unsigned* flags = nullptr;
    cudaGetSymbolAddress((void**)&flags, g_flags);

    float* preqg = S + O_PREQG;
    float* preqc = S + O_PREQC;
    float* plfw  = S + O_PLFW;
    float* plbw  = S + O_PLBW;
    float* feats = S + O_FEATS;
    float* prer  = S + O_PRER;
    float* prec  = S + O_PREC;
    float* ffw   = S + O_FFW;
    float* fbw   = S + O_FBW;
    float* fact  = S + O_FACT;
    float* atth  = S + O_ATTH;
    float* att   = S + O_ATT;
    float* gate  = S + O_GATE;
    float* h     = S + O_H;
    float* rh    = S + O_RH;
    float* u     = S + O_U;
    float* qvec  = S + O_QVEC;
    float* lh    = S + O_LH;
    float* lc    = S + O_LC;
    float* mem   = S + O_MEM;
    float* as_   = S + O_AS;
    float* ae_   = S + O_AE;
    float* outs0 = S + O_OUTS0;
    float* oute0 = S + O_OUTE0;
    float* P1    = S + O_P1;
    float* P2    = S + O_P2;
    int*   rmfw  = (int*)(S + O_RMFW);
    int*   rmbw  = (int*)(S + O_RMBW);

    // Launch #3 = 128-step dummy pk_agru: ncu (-s 5 with ~3 harness launches)
    // has captured my launch #3 every round since R5 — this finally profiles
    // the AGRU. Inputs are stale scratch (deterministic across replays);
    // outputs (P1/P2, outs0) are fully overwritten before semantic use.
    k_init<<<512, 256>>>(S);                                                     // 1 (also zeroes flags)
    k_rowmaps<<<128, 256>>>(input_ids, ilen, rmfw, rmbw);                        // 2
    pk_agru<<<128, 256>>>(Ur, Uc, prer, prec, gate, ilen, outs0, P1, P2, 128);   // 3 (profiled)

    gemm128<0><<<dim3(16,256), 256>>>(emb, 512, rmfw, lfW, 2048, lfb, plfw, 2048, 512);
    gemm128<0><<<dim3(16,256), 256>>>(emb, 512, rmbw, lbW, 2048, lbb, plbw, 2048, 512);
    k_zerou<<<1, 256>>>(flags);
    pk_lstm<<<128, 256>>>(lfW + 512L*2048, lbW + 512L*2048, plfw, plbw, ilen,
                          lh, lc, ffw, fbw);
    k_combine<<<512, 256>>>(fact, ffw, fbw);

    // question GRU
    gemm128<0><<<dim3(8,  16), 256>>>(emb, 512, question, qWg, 1024, qbg, preqg, 1024, 512);
    gemm128<0><<<dim3(4,  16), 256>>>(emb, 512, question, qWc,  512, qbc, preqc,  512, 512);
    k_zerou<<<1, 256>>>(flags);
    pk_gru<<<32, 256>>>(qWg + 512L*1024, qWc + 512L*512, preqg, preqc, qlen, h, rh, u);
    k_copy2<<<128, 256>>>(qvec, mem, h);

    // AGRU input-side precompute (hop-invariant)
    gemm128<0><<<dim3(4,256), 256>>>(fact, 512, nullptr, Wr, 512, br, prer, 512, 512);
    gemm128<0><<<dim3(4,256), 256>>>(fact, 512, nullptr, Wc, 512, bc, prec, 512, 512);

    // hops
    int cur = 0;
    for (int hop = 0; hop < 3; hop++){
        k_buildfeats<<<2048, 256>>>(feats, fact, qvec, mem + cur*32768);
        gemm128<2><<<dim3(4,256), 256>>>(feats, 3584, nullptr, aW1, 512, ab1, atth, 512, 3584);
        k_att2<<<512, 256>>>(atth, aW2, ab2, att);
        k_softmax<<<64, 256>>>(att, gate);

        k_zerou<<<1, 256>>>(flags);
        pk_agru<<<128, 256>>>(Ur, Uc, prer, prec, gate, ilen, h, P1, P2, 512);

        if (hop == 2){
            k_gather_rows<<<64, 256>>>(as_, emb, start);
            k_gather_rows<<<64, 256>>>(ae_, emb, start);
        }
        int nxt = cur ^ 1;
        k_catgemm<1><<<8, 256>>>(mem + cur*32768, h, qvec, as_, ae_,
                                 hopW + (long)hop*2560*512, hopB + hop*512,
                                 mem + nxt*32768, 2560);
        if (hop == 0){
            k_catgemm<0><<<8, 256>>>(mem + nxt*32768, qvec, qvec, qvec, qvec, osW, osB, outs0, 1024);
            k_catgemm<0><<<8, 256>>>(mem + nxt*32768, qvec, qvec, qvec, qvec, oeW, oeB, oute0, 1024);
            k_argmax_gather<<<64, 256>>>(outs0, emb, ae_);
            k_argmax_gather<<<64, 256>>>(oute0, emb, as_);
        }
        if (hop == 2){
            k_catgemm<0><<<8, 256>>>(mem + nxt*32768, qvec, qvec, qvec, qvec, osW, osB, out, 1024);
            k_catgemm<0><<<8, 256>>>(mem + nxt*32768, qvec, qvec, qvec, qvec, oeW, oeB, out + 32768, 1024);
        }
        cur = nxt;
    }
}

// round 17
// speedup vs baseline: 1.4313x; 1.4313x over previous
#include <cuda_runtime.h>
#include <math.h>

// ---------------------------------------------------------------------------
// Scratch arena (floats). feats overlays plfw/plbw (dead after pk_lstm).
// ---------------------------------------------------------------------------
#define SZ_PREQG   (2048L*1024)
#define SZ_PREQC   (2048L*512)
#define SZ_PLFW    (32768L*2048)
#define SZ_PLBW    (32768L*2048)
#define SZ_PRER    (32768L*512)
#define SZ_PREC    (32768L*512)
#define SZ_FFW     (32768L*512)
#define SZ_FBW     (32768L*512)
#define SZ_FACT    (32768L*512)
#define SZ_ATTH    (32768L*512)
#define SZ_ATT     (32768L)
#define SZ_GATE    (32768L)
#define SZ_H       (32768L)
#define SZ_RH      (32768L)
#define SZ_U       (32768L)
#define SZ_QVEC    (32768L)
#define SZ_LH      (131072L)
#define SZ_LC      (65536L)
#define SZ_MEM     (65536L)
#define SZ_AS      (32768L)
#define SZ_AE      (32768L)
#define SZ_OUTS0   (32768L)
#define SZ_OUTE0   (32768L)
#define SZ_RMFW    (32768L)
#define SZ_RMBW    (32768L)
#define SZ_P       (524288L)        // AGRU partials: [16 kt][512 n][64 b]

#define O_PREQG  0L
#define O_PREQC  (O_PREQG + SZ_PREQG)
#define O_PLFW   (O_PREQC + SZ_PREQC)
#define O_PLBW   (O_PLFW  + SZ_PLFW)
#define O_FEATS  O_PLFW
#define O_PRER   (O_PLBW  + SZ_PLBW)
#define O_PREC   (O_PRER  + SZ_PRER)
#define O_FFW    (O_PREC  + SZ_PREC)
#define O_FBW    (O_FFW   + SZ_FFW)
#define O_FACT   (O_FBW   + SZ_FBW)
#define O_ATTH   (O_FACT  + SZ_FACT)
#define O_ATT    (O_ATTH  + SZ_ATTH)
#define O_GATE   (O_ATT   + SZ_ATT)
#define O_H      (O_GATE  + SZ_GATE)
#define O_RH     (O_H     + SZ_H)
#define O_U      (O_RH    + SZ_RH)
#define O_QVEC   (O_U     + SZ_U)
#define O_LH     (O_QVEC  + SZ_QVEC)
#define O_LC     (O_LH    + SZ_LH)
#define O_MEM    (O_LC    + SZ_LC)
#define O_AS     (O_MEM   + SZ_MEM)
#define O_AE     (O_AS    + SZ_AS)
#define O_OUTS0  (O_AE    + SZ_AE)
#define O_OUTE0  (O_OUTS0 + SZ_OUTS0)
#define O_RMFW   (O_OUTE0 + SZ_OUTE0)
#define O_RMBW   (O_RMFW  + SZ_RMFW)
#define O_P1     (O_RMBW  + SZ_RMBW)
#define O_P2     (O_P1    + SZ_P)
#define SCR_TOTAL (O_P2 + SZ_P)

__device__ float g_scratch[SCR_TOTAL];
__device__ unsigned g_flags[2048];   // one flag per 32B sector: index = block*8

__device__ __forceinline__ float sigf(float x){ return 1.0f/(1.0f+expf(-x)); }

// packed fp32x2 FMA (exact fp32 per half)
__device__ __forceinline__ unsigned long long fma2(unsigned long long a,
                                                   unsigned long long b,
                                                   unsigned long long c){
    unsigned long long d;
    asm("fma.rn.f32x2 %0, %1, %2, %3;" : "=l"(d) : "l"(a), "l"(b), "l"(c));
    return d;
}
__device__ __forceinline__ float2 ull2f2(unsigned long long u){
    float2 f;
    asm("mov.b64 {%0, %1}, %2;" : "=f"(f.x), "=f"(f.y) : "l"(u));
    return f;
}
__device__ __forceinline__ unsigned long long dup2(float b){
    unsigned long long d;
    asm("mov.b64 %0, {%1, %1};" : "=l"(d) : "f"(b));
    return d;
}

// Decongested grid barrier: flags padded to one per 32B sector (no same-line
// poll pileup on two LTS slices) + nanosleep backoff (poll rate ~8x lower, so
// the release store and the observation polls don't queue behind poll floods).
__device__ __forceinline__ void flatbar(int nb, unsigned gen){
    __syncthreads();
    if (threadIdx.x == 0){
        asm volatile("st.release.gpu.global.u32 [%0], %1;"
                     :: "l"(g_flags + blockIdx.x*8), "r"(gen) : "memory");
    }
    if (threadIdx.x < nb){
        unsigned v;
        asm volatile("ld.acquire.gpu.global.u32 %0, [%1];"
                     : "=r"(v) : "l"(g_flags + threadIdx.x*8) : "memory");
        while (v < gen){
            __nanosleep(128);
            asm volatile("ld.acquire.gpu.global.u32 %0, [%1];"
                         : "=r"(v) : "l"(g_flags + threadIdx.x*8) : "memory");
        }
    }
    __syncthreads();
}

// ---------------------------------------------------------------------------
// tiny helpers
// ---------------------------------------------------------------------------
__global__ void k_init(float* __restrict__ S){
    long i = (long)blockIdx.x*256 + threadIdx.x;   // grid 512 -> 131072
    if (i < 32768){ S[O_H+i]=0.f; S[O_AS+i]=0.f; S[O_AE+i]=0.f; }
    if (i < 65536) S[O_LC+i]=0.f;
    S[O_LH+i]=0.f;
}
__global__ void k_zerou(unsigned* __restrict__ p){
    p[blockIdx.x*256 + threadIdx.x] = 0u;   // grid 8 -> 2048
}
__global__ void k_copy2(float* __restrict__ d1, float* __restrict__ d2, const float* __restrict__ s){
    int i = blockIdx.x*256 + threadIdx.x;
    float v = s[i];
    d1[i] = v; d2[i] = v;
}
__global__ void k_rowmaps(const int* __restrict__ ids, const int* __restrict__ ilen,
                          int* __restrict__ rmfw, int* __restrict__ rmbw){
    int idx = blockIdx.x*256 + threadIdx.x;
    int b = idx >> 9, t = idx & 511;
    rmfw[idx] = ids[idx];
    int L = ilen[b];
    int rt = (t < L) ? (L - 1 - t) : t;
    rmbw[idx] = ids[b*512 + rt];
}
__global__ void k_combine(float* __restrict__ dst, const float* __restrict__ a, const float* __restrict__ b){
    long i = (long)blockIdx.x*256 + threadIdx.x;
    float4 x = ((const float4*)a)[i];
    float4 y = ((const float4*)b)[i];
    ((float4*)dst)[i] = make_float4(x.x+y.x, x.y+y.y, x.z+y.z, x.w+y.w);
}
__global__ void k_gather_rows(float* __restrict__ dst, const float* __restrict__ emb, const int* __restrict__ idx){
    int b = blockIdx.x, tid = threadIdx.x;
    long r = idx[b];
    dst[b*512 + tid]       = emb[r*512 + tid];
    dst[b*512 + 256 + tid] = emb[r*512 + 256 + tid];
}
__global__ void k_argmax_gather(const float* __restrict__ logits, const float* __restrict__ emb, float* __restrict__ dst){
    __shared__ float sv[256];
    __shared__ int   si[256];
    int b = blockIdx.x, tid = threadIdx.x;
    float v0 = logits[b*512 + tid];
    float v1 = logits[b*512 + 256 + tid];
    float bv; int bi;
    if (v1 > v0){ bv = v1; bi = tid + 256; } else { bv = v0; bi = tid; }
    sv[tid] = bv; si[tid] = bi;
    __syncthreads();
    for (int s = 128; s > 0; s >>= 1){
        if (tid < s){
            float ov = sv[tid+s]; int oi = si[tid+s];
            if (ov > sv[tid] || (ov == sv[tid] && oi < si[tid])){ sv[tid] = ov; si[tid] = oi; }
        }
        __syncthreads();
    }
    long idx = si[0];
    dst[b*512 + tid]       = emb[idx*512 + tid];
    dst[b*512 + 256 + tid] = emb[idx*512 + 256 + tid];
}

// ---------------------------------------------------------------------------
// feature constructor
// ---------------------------------------------------------------------------
__device__ __forceinline__ float4 feat4(int k, const float4* fp, const float4* qp, const float4* mp){
    int seg = k >> 9, ki = (k & 511) >> 2;
    if (seg == 0) return fp[ki];
    if (seg == 1) return mp[ki];
    if (seg == 2) return qp[ki];
    float4 f = fp[ki];
    float4 q = (seg == 3 || seg == 5) ? qp[ki] : mp[ki];
    if (seg <= 4) return make_float4(f.x*q.x, f.y*q.y, f.z*q.z, f.w*q.w);
    return make_float4(fabsf(f.x-q.x), fabsf(f.y-q.y), fabsf(f.z-q.z), fabsf(f.w-q.w));
}

__global__ void k_buildfeats(float* __restrict__ feats, const float* __restrict__ fact,
                             const float* __restrict__ qvec, const float* __restrict__ mem){
    int m = blockIdx.y*2 + (threadIdx.x >> 7);
    int c = blockIdx.x*128 + (threadIdx.x & 127);
    int b = m >> 9;
    const float4* fp = (const float4*)(fact + (long)m*512);
    const float4* qp = (const float4*)(qvec + (long)b*512);
    const float4* mp = (const float4*)(mem  + (long)b*512);
    float4 v = feat4(c*4, fp, qp, mp);
    ((float4*)(feats + (long)m*3584))[c] = v;
}

// ---------------------------------------------------------------------------
// Big GEMM v3 (R8)
// ---------------------------------------------------------------------------
template<int ACT>
__global__ void __launch_bounds__(256) gemm128(
    const float* __restrict__ A, int lda, const int* __restrict__ rowmap,
    const float* __restrict__ B, int ldb,
    const float* __restrict__ bias,
    float* __restrict__ C, int ldc, int K)
{
    __shared__ float As[2][16][132];
    __shared__ float Bs[2][16][132];
    const int m0 = blockIdx.y*128, n0 = blockIdx.x*128;
    const int tid = threadIdx.x;
    const int tx = tid & 15, ty = tid >> 4;
    const int arow = tid >> 1, kg = (tid & 1)*8;
    const int brow = tid >> 4, bcol = (tid & 15)*8;
    long ar = rowmap ? (long)rowmap[m0 + arow] : (long)(m0 + arow);
    const float* Ap = A + ar*lda;
    const float* Bp = B + (long)brow*ldb + n0 + bcol;
    const int nc = K >> 4;

    unsigned long long acc[4][8];
    #pragma unroll
    for (int i = 0; i < 4; i++)
        #pragma unroll
        for (int j = 0; j < 8; j++) acc[i][j] = 0ull;

    float4 aR0 = *(const float4*)(Ap + kg);
    float4 aR1 = *(const float4*)(Ap + kg + 4);
    float4 bR0 = *(const float4*)(Bp);
    float4 bR1 = *(const float4*)(Bp + 4);
    {
        As[0][kg+0][arow]=aR0.x; As[0][kg+1][arow]=aR0.y;
        As[0][kg+2][arow]=aR0.z; As[0][kg+3][arow]=aR0.w;
        As[0][kg+4][arow]=aR1.x; As[0][kg+5][arow]=aR1.y;
        As[0][kg+6][arow]=aR1.z; As[0][kg+7][arow]=aR1.w;
        *(float4*)&Bs[0][brow][bcol]     = bR0;
        *(float4*)&Bs[0][brow][bcol + 4] = bR1;
    }
    __syncthreads();

    for (int c = 0; c < nc; c++){
        const int s = c & 1;
        if (c + 1 < nc){
            int k0 = (c+1) << 4;
            aR0 = *(const float4*)(Ap + k0 + kg);
            aR1 = *(const float4*)(Ap + k0 + kg + 4);
            bR0 = *(const float4*)(Bp + (long)k0*ldb);
            bR1 = *(const float4*)(Bp + (long)k0*ldb + 4);
        }
        #pragma unroll
        for (int kk = 0; kk < 16; kk++){
            unsigned long long a2[4];
            *(float4*)(a2)   = *(const float4*)&As[s][kk][ty*8];
            *(float4*)(a2+2) = *(const float4*)&As[s][kk][ty*8+4];
            float bsc[8];
            *(float4*)(bsc)   = *(const float4*)&Bs[s][kk][tx*8];
            *(float4*)(bsc+4) = *(const float4*)&Bs[s][kk][tx*8+4];
            #pragma unroll
            for (int j = 0; j < 8; j++){
                unsigned long long b2 = dup2(bsc[j]);
                #pragma unroll
                for (int i = 0; i < 4; i++)
                    acc[i][j] = fma2(a2[i], b2, acc[i][j]);
            }
        }
        if (c + 1 < nc){
            const int d = s ^ 1;
            As[d][kg+0][arow]=aR0.x; As[d][kg+1][arow]=aR0.y;
            As[d][kg+2][arow]=aR0.z; As[d][kg+3][arow]=aR0.w;
            As[d][kg+4][arow]=aR1.x; As[d][kg+5][arow]=aR1.y;
            As[d][kg+6][arow]=aR1.z; As[d][kg+7][arow]=aR1.w;
            *(float4*)&Bs[d][brow][bcol]     = bR0;
            *(float4*)&Bs[d][brow][bcol + 4] = bR1;
            __syncthreads();
        }
    }
    float bl[8];
    *(float4*)(bl)   = *(const float4*)&bias[n0 + tx*8];
    *(float4*)(bl+4) = *(const float4*)&bias[n0 + tx*8 + 4];
    #pragma unroll
    for (int i = 0; i < 4; i++){
        float lo[8], hi[8];
        #pragma unroll
        for (int j = 0; j < 8; j++){
            float2 v = ull2f2(acc[i][j]);
            lo[j] = v.x + bl[j];
            hi[j] = v.y + bl[j];
            if (ACT == 2){ lo[j] = tanhf(lo[j]); hi[j] = tanhf(hi[j]); }
        }
        long me = m0 + ty*8 + 2*i, mo = me + 1;
        *(float4*)&C[me*ldc + n0 + tx*8]     = *(float4*)(lo);
        *(float4*)&C[me*ldc + n0 + tx*8 + 4] = *(float4*)(lo+4);
        *(float4*)&C[mo*ldc + n0 + tx*8]     = *(float4*)(hi);
        *(float4*)&C[mo*ldc + n0 + tx*8 + 4] = *(float4*)(hi+4);
    }
}

__global__ void k_att2(const float* __restrict__ atth, const float* __restrict__ W2,
                       const float* __restrict__ b2, float* __restrict__ att){
    int m = blockIdx.x*8 + (threadIdx.x >> 5);
    int lane = threadIdx.x & 31;
    const float* row = atth + (long)m*512;
    float s = 0.f;
    #pragma unroll
    for (int i = 0; i < 16; i++) s = fmaf(row[lane + i*32], W2[lane + i*32], s);
    #pragma unroll
    for (int o = 16; o > 0; o >>= 1) s += __shfl_xor_sync(0xffffffffu, s, o);
    if (lane == 0) att[m] = s + b2[0];
}

__global__ void k_softmax(const float* __restrict__ att, float* __restrict__ gate){
    __shared__ float red[256];
    int b = blockIdx.x, tid = threadIdx.x;
    float v0 = att[b*512 + tid], v1 = att[b*512 + 256 + tid];
    red[tid] = fmaxf(v0, v1);
    __syncthreads();
    for (int s = 128; s > 0; s >>= 1){ if (tid < s) red[tid] = fmaxf(red[tid], red[tid+s]); __syncthreads(); }
    float mx = red[0];
    __syncthreads();
    float e0 = expf(v0 - mx), e1 = expf(v1 - mx);
    red[tid] = e0 + e1;
    __syncthreads();
    for (int s = 128; s > 0; s >>= 1){ if (tid < s) red[tid] += red[tid+s]; __syncthreads(); }
    float inv = 1.f/red[0];
    gate[b*512 + tid]       = e0*inv;
    gate[b*512 + 256 + tid] = e1*inv;
}

// ---------------------------------------------------------------------------
// Persistent question GRU (R8)
// ---------------------------------------------------------------------------
__global__ void __launch_bounds__(256) pk_gru(
    const float* __restrict__ Wg, const float* __restrict__ Wc,
    const float* __restrict__ preg, const float* __restrict__ prec,
    const int* __restrict__ qlen,
    float* __restrict__ h, float* __restrict__ rh, float* __restrict__ u)
{
    __shared__ float As[16][64];
    __shared__ float Bs[16][32];
    const int tid = threadIdx.x, bx = blockIdx.x;
    const int tx = tid & 31, ty = tid >> 5;
    const int arow = tid >> 2, acol = (tid & 3)*4;
    unsigned gen = 0;
    for (int t = 0; t < 32; t++){
        {
            const int n0 = bx*32;
            float acc[8] = {};
            for (int k0 = 0; k0 < 512; k0 += 16){
                float4 a4 = __ldcg((const float4*)(h + arow*512 + k0 + acol));
                As[acol+0][arow]=a4.x; As[acol+1][arow]=a4.y;
                As[acol+2][arow]=a4.z; As[acol+3][arow]=a4.w;
                if (tid < 128){
                    int kk = tid >> 3, c4 = (tid & 7)*4;
                    *(float4*)&Bs[kk][c4] = *(const float4*)(Wg + (long)(k0+kk)*1024 + n0 + c4);
                }
                __syncthreads();
                #pragma unroll
                for (int kk = 0; kk < 16; kk++){
                    float ra[8];
                    *(float4*)(ra)   = *(const float4*)&As[kk][ty*8];
                    *(float4*)(ra+4) = *(const float4*)&As[kk][ty*8+4];
                    float rb = Bs[kk][tx];
                    #pragma unroll
                    for (int i = 0; i < 8; i++) acc[i] = fmaf(ra[i], rb, acc[i]);
                }
                __syncthreads();
            }
            int n = n0 + tx;
            #pragma unroll
            for (int i = 0; i < 8; i++){
                int b = ty*8 + i;
                float z = acc[i] + preg[((long)b*32 + t)*1024 + n];
                float s = sigf(z);
                if (n < 512) __stcg(rh + b*512 + n, s * __ldcg(h + b*512 + n));
                else         __stcg(u + b*512 + (n - 512), s);
            }
        }
        flatbar(32, ++gen);
        if (bx < 16){
            const int n0 = bx*32;
            float acc[8] = {};
            for (int k0 = 0; k0 < 512; k0 += 16){
                float4 a4 = __ldcg((const float4*)(rh + arow*512 + k0 + acol));
                As[acol+0][arow]=a4.x; As[acol+1][arow]=a4.y;
                As[acol+2][arow]=a4.z; As[acol+3][arow]=a4.w;
                if (tid < 128){
                    int kk = tid >> 3, c4 = (tid & 7)*4;
                    *(float4*)&Bs[kk][c4] = *(const float4*)(Wc + (long)(k0+kk)*512 + n0 + c4);
                }
                __syncthreads();
                #pragma unroll
                for (int kk = 0; kk < 16; kk++){
                    float ra[8];
                    *(float4*)(ra)   = *(const float4*)&As[kk][ty*8];
                    *(float4*)(ra+4) = *(const float4*)&As[kk][ty*8+4];
                    float rb = Bs[kk][tx];
                    #pragma unroll
                    for (int i = 0; i < 8; i++) acc[i] = fmaf(ra[i], rb, acc[i]);
                }
                __syncthreads();
            }
            int n = n0 + tx;
            #pragma unroll
            for (int i = 0; i < 8; i++){
                int b = ty*8 + i;
                float c = tanhf(acc[i] + prec[((long)b*32 + t)*512 + n]);
                float uu = __ldcg(u + b*512 + n);
                float ho = __ldcg(h + b*512 + n);
                float hn = (t < qlen[b]) ? (uu*ho + (1.f - uu)*c) : ho;
                __stcg(h + b*512 + n, hn);
            }
        }
        flatbar(32, ++gen);
    }
}

// ---------------------------------------------------------------------------
// Persistent bi-LSTM (R8)
// ---------------------------------------------------------------------------
__global__ void __launch_bounds__(256) pk_lstm(
    const float* __restrict__ Wfwh, const float* __restrict__ Wbwh,
    const float* __restrict__ prefw, const float* __restrict__ prebw,
    const int* __restrict__ ilen,
    float* __restrict__ lh, float* __restrict__ lc,
    float* __restrict__ ffw, float* __restrict__ fbw)
{
    __shared__ float As[16][64];
    __shared__ float Bs[16][32];
    __shared__ float zs[64][32];
    const int tid = threadIdx.x;
    const int dir = blockIdx.x >> 6;
    const int hc8 = (blockIdx.x & 63)*8;
    const float* Wh  = dir ? Wbwh : Wfwh;
    const float* pre = dir ? prebw : prefw;
    float* cbuf = lc + dir*32768;
    float* outp = dir ? fbw : ffw;
    const int tx = tid & 31, ty = tid >> 5;
    const int arow = tid >> 2, acol = (tid & 3)*4;
    const int eb0 = (tid*2) >> 3,     ej0 = (tid*2) & 7;
    const int eb1 = (tid*2+1) >> 3,   ej1 = (tid*2+1) & 7;
    const int ehc0 = hc8 + ej0, ehc1 = hc8 + ej1;
    const int L0 = ilen[eb0], L1 = ilen[eb1];
    unsigned gen = 0;
    for (int t = 0; t < 512; t++){
        const int par = t & 1;
        const float* hin = lh + par*65536 + dir*32768;
        float* hout = lh + (par^1)*65536 + dir*32768;

        long pr0 = ((long)eb0*512 + t)*2048;
        long pr1 = ((long)eb1*512 + t)*2048;
        float pz0_i = __ldcg(pre + pr0 + ehc0);
        float pz0_j = __ldcg(pre + pr0 + 512 + ehc0);
        float pz0_f = __ldcg(pre + pr0 + 1024 + ehc0);
        float pz0_o = __ldcg(pre + pr0 + 1536 + ehc0);
        float pz1_i = __ldcg(pre + pr1 + ehc1);
        float pz1_j = __ldcg(pre + pr1 + 512 + ehc1);
        float pz1_f = __ldcg(pre + pr1 + 1024 + ehc1);
        float pz1_o = __ldcg(pre + pr1 + 1536 + ehc1);
        float hold0 = __ldcg(hin + eb0*512 + ehc0);
        float hold1 = __ldcg(hin + eb1*512 + ehc1);

        float acc[8] = {};
        for (int k0 = 0; k0 < 512; k0 += 16){
            float4 a4 = __ldcg((const float4*)(hin + arow*512 + k0 + acol));
            As[acol+0][arow]=a4.x; As[acol+1][arow]=a4.y;
            As[acol+2][arow]=a4.z; As[acol+3][arow]=a4.w;
            if (tid < 128){
                int kk = tid >> 3, rem = tid & 7;
                int gg = rem >> 1, h4 = (rem & 1)*4;
                *(float4*)&Bs[kk][gg*8 + h4] =
                    *(const float4*)(Wh + (long)(k0+kk)*2048 + gg*512 + hc8 + h4);
            }
            __syncthreads();
            #pragma unroll
            for (int kk = 0; kk < 16; kk++){
                float ra[8];
                *(float4*)(ra)   = *(const float4*)&As[kk][ty*8];
                *(float4*)(ra+4) = *(const float4*)&As[kk][ty*8+4];
                float rb = Bs[kk][tx];
                #pragma unroll
                for (int i = 0; i < 8; i++) acc[i] = fmaf(ra[i], rb, acc[i]);
            }
            __syncthreads();
        }
        #pragma unroll
        for (int i = 0; i < 8; i++) zs[ty*8 + i][tx] = acc[i];
        __syncthreads();
        {
            float zi = zs[eb0][ej0]      + pz0_i;
            float zj = zs[eb0][8 + ej0]  + pz0_j;
            float zf = zs[eb0][16 + ej0] + pz0_f;
            float zo = zs[eb0][24 + ej0] + pz0_o;
            float c_old = cbuf[eb0*512 + ehc0];
            float cn = sigf(zf + 1.f)*c_old + sigf(zi)*tanhf(zj);
            float hn = sigf(zo)*tanhf(cn);
            bool m = t < L0;
            __stcg(hout + eb0*512 + ehc0, m ? hn : hold0);
            cbuf[eb0*512 + ehc0] = m ? cn : c_old;
            int wt = dir ? (m ? (L0 - 1 - t) : t) : t;
            __stcg(outp + ((long)eb0*512 + wt)*512 + ehc0, m ? hn : 0.f);
        }
        {
            float zi = zs[eb1][ej1]      + pz1_i;
            float zj = zs[eb1][8 + ej1]  + pz1_j;
            float zf = zs[eb1][16 + ej1] + pz1_f;
            float zo = zs[eb1][24 + ej1] + pz1_o;
            float c_old = cbuf[eb1*512 + ehc1];
            float cn = sigf(zf + 1.f)*c_old + sigf(zi)*tanhf(zj);
            float hn = sigf(zo)*tanhf(cn);
            bool m = t < L1;
            __stcg(hout + eb1*512 + ehc1, m ? hn : hold1);
            cbuf[eb1*512 + ehc1] = m ? cn : c_old;
            int wt = dir ? (m ? (L1 - 1 - t) : t) : t;
            __stcg(outp + ((long)eb1*512 + wt)*512 + ehc1, m ? hn : 0.f);
        }
        flatbar(128, ++gen);
    }
}

// ---------------------------------------------------------------------------
// Persistent AGRU v3 (R8): 64 blocks = 4 nt (128 cols) x 16 kt (32 k).
// ---------------------------------------------------------------------------
__global__ void __launch_bounds__(256) pk_agru(
    const float* __restrict__ Ur, const float* __restrict__ Uc,
    const float* __restrict__ prer, const float* __restrict__ prec,
    const float* __restrict__ gate, const int* __restrict__ ilen,
    float* __restrict__ h, float* __restrict__ P1, float* __restrict__ P2)
{
    __shared__ float Urs[32][132];
    __shared__ float Ucs[32][132];
    __shared__ float hs[32][72];
    __shared__ float rhs[32][72];
    __shared__ int   ilens[64];

    const int tid = threadIdx.x;
    const int nt = blockIdx.x & 3;
    const int kt = blockIdx.x >> 2;
    const int kbase = kt*32, nbase = nt*128;

    const int ty = tid >> 5;
    const int tx = tid & 31;
    const int nl = tid >> 3;
    const int bb = (tid & 7)*8;
    const int ngl = kbase + nl;

    for (int i = tid; i < 32*128; i += 256){
        int k = i >> 7, n = i & 127;
        Urs[k][n] = Ur[(long)(kbase + k)*512 + nbase + n];
        Ucs[k][n] = Uc[(long)(kbase + k)*512 + nbase + n];
    }
    for (int i = tid; i < 32*64; i += 256) hs[i >> 6][i & 63] = 0.f;
    if (tid < 64) ilens[tid] = ilen[tid];
    __syncthreads();

    unsigned gen = 0;
    for (int t = 0; t < 512; t++){
        {
            unsigned long long acc[4][4];
            #pragma unroll
            for (int j = 0; j < 4; j++)
                #pragma unroll
                for (int p = 0; p < 4; p++) acc[j][p] = 0ull;
            #pragma unroll 8
            for (int k = 0; k < 32; k++){
                unsigned long long ap[4];
                *(float4*)(ap)   = *(const float4*)&hs[k][8*ty];
                *(float4*)(ap+2) = *(const float4*)&hs[k][8*ty+4];
                float4 bv = *(const float4*)&Urs[k][4*tx];
                unsigned long long b0 = dup2(bv.x), b1 = dup2(bv.y);
                unsigned long long b2 = dup2(bv.z), b3 = dup2(bv.w);
                #pragma unroll
                for (int p = 0; p < 4; p++){
                    acc[0][p] = fma2(ap[p], b0, acc[0][p]);
                    acc[1][p] = fma2(ap[p], b1, acc[1][p]);
                    acc[2][p] = fma2(ap[p], b2, acc[2][p]);
                    acc[3][p] = fma2(ap[p], b3, acc[3][p]);
                }
            }
            #pragma unroll
            for (int j = 0; j < 4; j++){
                long base = (long)kt*32768 + (long)(nbase + 4*tx + j)*64 + 8*ty;
                __stcg((float4*)(P1 + base),     *(float4*)&acc[j][0]);
                __stcg((float4*)(P1 + base + 4), *(float4*)&acc[j][2]);
            }
        }
        flatbar(64, ++gen);
        {
            float z[8];
            #pragma unroll
            for (int i = 0; i < 8; i++)
                z[i] = __ldcg(prer + ((long)(bb+i)*512 + t)*512 + ngl);
            #pragma unroll
            for (int j = 0; j < 16; j++){
                const float* pp = P1 + (long)j*32768 + (long)ngl*64 + bb;
                float4 p0 = __ldcg((const float4*)pp);
                float4 p1 = __ldcg((const float4*)(pp + 4));
                z[0] += p0.x; z[1] += p0.y; z[2] += p0.z; z[3] += p0.w;
                z[4] += p1.x; z[5] += p1.y; z[6] += p1.z; z[7] += p1.w;
            }
            float hold[8];
            *(float4*)(hold)   = *(const float4*)&hs[nl][bb];
            *(float4*)(hold+4) = *(const float4*)&hs[nl][bb+4];
            float rv[8];
            #pragma unroll
            for (int i = 0; i < 8; i++) rv[i] = sigf(z[i]) * hold[i];
            *(float4*)&rhs[nl][bb]   = *(float4*)(rv);
            *(float4*)&rhs[nl][bb+4] = *(float4*)(rv+4);
        }
        __syncthreads();
        {
            unsigned long long acc[4][4];
            #pragma unroll
            for (int j = 0; j < 4; j++)
                #pragma unroll
                for (int p = 0; p < 4; p++) acc[j][p] = 0ull;
            #pragma unroll 8
            for (int k = 0; k < 32; k++){
                unsigned long long ap[4];
                *(float4*)(ap)   = *(const float4*)&rhs[k][8*ty];
                *(float4*)(ap+2) = *(const float4*)&rhs[k][8*ty+4];
                float4 bv = *(const float4*)&Ucs[k][4*tx];
                unsigned long long b0 = dup2(bv.x), b1 = dup2(bv.y);
                unsigned long long b2 = dup2(bv.z), b3 = dup2(bv.w);
                #pragma unroll
                for (int p = 0; p < 4; p++){
                    acc[0][p] = fma2(ap[p], b0, acc[0][p]);
                    acc[1][p] = fma2(ap[p], b1, acc[1][p]);
                    acc[2][p] = fma2(ap[p], b2, acc[2][p]);
                    acc[3][p] = fma2(ap[p], b3, acc[3][p]);
                }
            }
            #pragma unroll
            for (int j = 0; j < 4; j++){
                long base = (long)kt*32768 + (long)(nbase + 4*tx + j)*64 + 8*ty;
                __stcg((float4*)(P2 + base),     *(float4*)&acc[j][0]);
                __stcg((float4*)(P2 + base + 4), *(float4*)&acc[j][2]);
            }
        }
        flatbar(64, ++gen);
        {
            float z[8], gg[8];
            #pragma unroll
            for (int i = 0; i < 8; i++){
                z[i]  = __ldcg(prec + ((long)(bb+i)*512 + t)*512 + ngl);
                gg[i] = __ldg(gate + (bb+i)*512 + t);
            }
            #pragma unroll
            for (int j = 0; j < 16; j++){
                const float* pp = P2 + (long)j*32768 + (long)ngl*64 + bb;
                float4 p0 = __ldcg((const float4*)pp);
                float4 p1 = __ldcg((const float4*)(pp + 4));
                z[0] += p0.x; z[1] += p0.y; z[2] += p0.z; z[3] += p0.w;
                z[4] += p1.x; z[5] += p1.y; z[6] += p1.z; z[7] += p1.w;
            }
            float hold[8];
            *(float4*)(hold)   = *(const float4*)&hs[nl][bb];
            *(float4*)(hold+4) = *(const float4*)&hs[nl][bb+4];
            float hv[8];
            #pragma unroll
            for (int i = 0; i < 8; i++){
                float hh = tanhf(z[i]);
                bool m = t < ilens[bb+i];
                hv[i] = m ? (gg[i]*hh + (1.f - gg[i])*hold[i]) : hold[i];
            }
            *(float4*)&hs[nl][bb]   = *(float4*)(hv);
            *(float4*)&hs[nl][bb+4] = *(float4*)(hv+4);
        }
        __syncthreads();
    }
    if (nt == 0){
        #pragma unroll
        for (int i = 0; i < 8; i++)
            __stcg(h + (long)(bb+i)*512 + ngl, hs[nl][bb+i]);
    }
}

// ---------------------------------------------------------------------------
// Concat-A GEMM (R8)
// ---------------------------------------------------------------------------
template<int ACT>
__global__ void __launch_bounds__(256) k_catgemm(
    const float* __restrict__ p0, const float* __restrict__ p1,
    const float* __restrict__ p2, const float* __restrict__ p3,
    const float* __restrict__ p4,
    const float* __restrict__ W, const float* __restrict__ bias,
    float* __restrict__ C, int K)
{
    const float* segs[5] = {p0, p1, p2, p3, p4};
    __shared__ float As[16][64];
    __shared__ float Bs[16][64];
    const int n0 = blockIdx.x*64;
    const int tid = threadIdx.x;
    const int tx = tid & 31, ty = tid >> 5;
    const int arow = tid >> 2, acol = (tid & 3)*4;
    const int brow = tid >> 4, bcol = (tid & 15)*4;
    float acc[8][2] = {};
    for (int k0 = 0; k0 < K; k0 += 16){
        int k = k0 + acol;
        const float* sp = segs[k >> 9];
        float4 a4 = *(const float4*)(sp + arow*512 + (k & 511));
        As[acol+0][arow] = a4.x; As[acol+1][arow] = a4.y;
        As[acol+2][arow] = a4.z; As[acol+3][arow] = a4.w;
        *(float4*)&Bs[brow][bcol] = *(const float4*)(W + (long)(k0+brow)*512 + n0 + bcol);
        __syncthreads();
        #pragma unroll
        for (int kk = 0; kk < 16; kk++){
            float ra[8];
            *(float4*)(ra)   = *(const float4*)&As[kk][ty*8];
            *(float4*)(ra+4) = *(const float4*)&As[kk][ty*8+4];
            float2 rb = *(const float2*)&Bs[kk][tx*2];
            #pragma unroll
            for (int i = 0; i < 8; i++){
                acc[i][0] = fmaf(ra[i], rb.x, acc[i][0]);
                acc[i][1] = fmaf(ra[i], rb.y, acc[i][1]);
            }
        }
        __syncthreads();
    }
    #pragma unroll
    for (int i = 0; i < 8; i++){
        int b = ty*8 + i;
        #pragma unroll
        for (int j = 0; j < 2; j++){
            int n = n0 + tx*2 + j;
            float v = acc[i][j] + bias[n];
            if (ACT == 1) v = fmaxf(v, 0.f);
            C[b*512 + n] = v;
        }
    }
}

// ---------------------------------------------------------------------------
// host launcher (R8 order)
// ---------------------------------------------------------------------------
extern "C" void kernel_launch(void* const* d_in, const int* in_sizes, int n_in,
                              void* d_out, int out_size)
{
    (void)in_sizes; (void)n_in; (void)out_size;
    const int*   question  = (const int*)  d_in[0];
    const int*   input_ids = (const int*)  d_in[1];
    const int*   qlen      = (const int*)  d_in[2];
    const int*   ilen      = (const int*)  d_in[3];
    const int*   start     = (const int*)  d_in[4];
    const float* emb       = (const float*)d_in[5];
    const float* qWg       = (const float*)d_in[6];
    const float* qbg       = (const float*)d_in[7];
    const float* qWc       = (const float*)d_in[8];
    const float* qbc       = (const float*)d_in[9];
    const float* lfW       = (const float*)d_in[10];
    const float* lfb       = (const float*)d_in[11];
    const float* lbW       = (const float*)d_in[12];
    const float* lbb       = (const float*)d_in[13];
    const float* aW1       = (const float*)d_in[14];
    const float* ab1       = (const float*)d_in[15];
    const float* aW2       = (const float*)d_in[16];
    const float* ab2       = (const float*)d_in[17];
    const float* Wr        = (const float*)d_in[18];
    const float* Ur        = (const float*)d_in[19];
    const float* br        = (const float*)d_in[20];
    const float* Wc        = (const float*)d_in[21];
    const float* Uc        = (const float*)d_in[22];
    const float* bc        = (const float*)d_in[23];
    const float* hopW      = (const float*)d_in[24];
    const float* hopB      = (const float*)d_in[25];
    const float* osW       = (const float*)d_in[26];
    const float* osB       = (const float*)d_in[27];
    const float* oeW       = (const float*)d_in[28];
    const float* oeB       = (const float*)d_in[29];
    float* out = (float*)d_out;

    float* S = nullptr;
    cudaGetSymbolAddress((void**)&S, g_scratch);
    unsigned* flags = nullptr;
    cudaGetSymbolAddress((void**)&flags, g_flags);

    float* preqg = S + O_PREQG;
    float* preqc = S + O_PREQC;
    float* plfw  = S + O_PLFW;
    float* plbw  = S + O_PLBW;
    float* feats = S + O_FEATS;
    float* prer  = S + O_PRER;
    float* prec  = S + O_PREC;
    float* ffw   = S + O_FFW;
    float* fbw   = S + O_FBW;
    float* fact  = S + O_FACT;
    float* atth  = S + O_ATTH;
    float* att   = S + O_ATT;
    float* gate  = S + O_GATE;
    float* h     = S + O_H;
    float* rh    = S + O_RH;
    float* u     = S + O_U;
    float* qvec  = S + O_QVEC;
    float* lh    = S + O_LH;
    float* lc    = S + O_LC;
    float* mem   = S + O_MEM;
    float* as_   = S + O_AS;
    float* ae_   = S + O_AE;
    float* outs0 = S + O_OUTS0;
    float* oute0 = S + O_OUTE0;
    float* P1    = S + O_P1;
    float* P2    = S + O_P2;
    int*   rmfw  = (int*)(S + O_RMFW);
    int*   rmbw  = (int*)(S + O_RMBW);

    k_init<<<512, 256>>>(S);
    k_rowmaps<<<128, 256>>>(input_ids, ilen, rmfw, rmbw);
    gemm128<0><<<dim3(16,256), 256>>>(emb, 512, rmfw, lfW, 2048, lfb, plfw, 2048, 512);
    gemm128<0><<<dim3(16,256), 256>>>(emb, 512, rmbw, lbW, 2048, lbb, plbw, 2048, 512);
    k_zerou<<<8, 256>>>(flags);
    pk_lstm<<<128, 256>>>(lfW + 512L*2048, lbW + 512L*2048, plfw, plbw, ilen,
                          lh, lc, ffw, fbw);
    k_combine<<<16384, 256>>>(fact, ffw, fbw);

    // question GRU
    gemm128<0><<<dim3(8,  16), 256>>>(emb, 512, question, qWg, 1024, qbg, preqg, 1024, 512);
    gemm128<0><<<dim3(4,  16), 256>>>(emb, 512, question, qWc,  512, qbc, preqc,  512, 512);
    k_zerou<<<8, 256>>>(flags);
    pk_gru<<<32, 256>>>(qWg + 512L*1024, qWc + 512L*512, preqg, preqc, qlen, h, rh, u);
    k_copy2<<<128, 256>>>(qvec, mem, h);

    // AGRU input-side precompute (hop-invariant)
    gemm128<0><<<dim3(4,256), 256>>>(fact, 512, nullptr, Wr, 512, br, prer, 512, 512);
    gemm128<0><<<dim3(4,256), 256>>>(fact, 512, nullptr, Wc, 512, bc, prec, 512, 512);

    // hops
    int cur = 0;
    for (int hop = 0; hop < 3; hop++){
        k_buildfeats<<<dim3(7,16384), 256>>>(feats, fact, qvec, mem + cur*32768);
        gemm128<2><<<dim3(4,256), 256>>>(feats, 3584, nullptr, aW1, 512, ab1, atth, 512, 3584);
        k_att2<<<4096, 256>>>(atth, aW2, ab2, att);
        k_softmax<<<64, 256>>>(att, gate);

        k_zerou<<<8, 256>>>(flags);
        pk_agru<<<64, 256>>>(Ur, Uc, prer, prec, gate, ilen, h, P1, P2);

        if (hop == 2){
            k_gather_rows<<<64, 256>>>(as_, emb, start);
            k_gather_rows<<<64, 256>>>(ae_, emb, start);
        }
        int nxt = cur ^ 1;
        k_catgemm<1><<<8, 256>>>(mem + cur*32768, h, qvec, as_, ae_,
                                 hopW + (long)hop*2560*512, hopB + hop*512,
                                 mem + nxt*32768, 2560);
        if (hop == 0){
            k_catgemm<0><<<8, 256>>>(mem + nxt*32768, qvec, qvec, qvec, qvec, osW, osB, outs0, 1024);
            k_catgemm<0><<<8, 256>>>(mem + nxt*32768, qvec, qvec, qvec, qvec, oeW, oeB, oute0, 1024);
            k_argmax_gather<<<64, 256>>>(outs0, emb, ae_);
            k_argmax_gather<<<64, 256>>>(oute0, emb, as_);
        }
        if (hop == 2){
            k_catgemm<0><<<8, 256>>>(mem + nxt*32768, qvec, qvec, qvec, qvec, osW, osB, out, 1024);
            k_catgemm<0><<<8, 256>>>(mem + nxt*32768, qvec, qvec, qvec, qvec, oeW, oeB, out + 32768, 1024);
        }
        cur = nxt;
    }
}